// round 16
// baseline (speedup 1.0000x reference)
#include <cuda_runtime.h>
#include <cuda_fp16.h>
#include <math.h>
#include <stdint.h>

#define BB 2048
#define KK 256
#define AD 512
#define IN 768
#define NUME 100000

#define TM 64
#define TN 64
#define TKC 64
#define NSTAGE 3
#define A_ST_B (TM * 128)
#define B_ST_B (TN * 128)
#define GEMM_SMEM (NSTAGE * (A_ST_B + B_ST_B))   // 49152 B

#define NGEMM 256          // GEMM CTAs per launch
#define NCONV 320          // converter CTAs per launch
#define EE_TOT ((size_t)NUME * 256)              // 25,600,000 elems

// ---------------- scratch (device globals: no allocs allowed) ----------------
__device__ __half g_A1 [(size_t)BB * 1536];   // split concat(E,H,Q) [hi|lo]
__device__ __half g_W1s[(size_t)AD * 1536];   // split W1            [hi|hi]
__device__ __half g_A2 [(size_t)BB * 1024];
__device__ __half g_W2s[(size_t)AD * 1024];
__device__ __half g_A3 [(size_t)BB * 512];
__device__ __half g_Ers[(size_t)512 * 512];
__device__ __half g_Ee [EE_TOT];              // fp16 emb_e (51.2 MB)
__device__ float g_X2e[(size_t)BB * 256];
__device__ float g_P  [(size_t)BB * 512];

// ---------------- helpers ----------------
__device__ __forceinline__ uint32_t smem_u32(const void* p) {
    uint32_t a;
    asm("{ .reg .u64 t; cvta.to.shared.u64 t, %1; cvt.u32.u64 %0, t; }" : "=r"(a) : "l"(p));
    return a;
}
#define CP_ASYNC16(dst, src) \
    asm volatile("cp.async.cg.shared.global [%0], [%1], 16;" :: "r"(dst), "l"(src) : "memory")
#define CP_COMMIT()  asm volatile("cp.async.commit_group;" ::: "memory")
#define CP_WAIT(n)   asm volatile("cp.async.wait_group %0;" :: "n"(n) : "memory")

__device__ __forceinline__ void ldsm_x4(uint32_t* r, uint32_t addr) {
    asm volatile("ldmatrix.sync.aligned.m8n8.x4.shared.b16 {%0,%1,%2,%3}, [%4];"
                 : "=r"(r[0]), "=r"(r[1]), "=r"(r[2]), "=r"(r[3]) : "r"(addr));
}
__device__ __forceinline__ void mma16816(float* c, const uint32_t* a, const uint32_t* b) {
    asm volatile(
        "mma.sync.aligned.m16n8k16.row.col.f32.f16.f16.f32 "
        "{%0,%1,%2,%3}, {%4,%5,%6,%7}, {%8,%9}, {%0,%1,%2,%3};"
        : "+f"(c[0]), "+f"(c[1]), "+f"(c[2]), "+f"(c[3])
        : "r"(a[0]), "r"(a[1]), "r"(a[2]), "r"(a[3]), "r"(b[0]), "r"(b[1]));
}
__device__ __forceinline__ uint32_t swz(int row, int seg) {
    return (uint32_t)(row * 128 + ((seg ^ (row & 7)) << 4));
}
__device__ __forceinline__ void split_store_A(float4 v, __half* d, int Koff) {
    __align__(8) __half hh[4], ll[4];
    hh[0] = __float2half_rn(v.x); ll[0] = __float2half_rn(v.x - __half2float(hh[0]));
    hh[1] = __float2half_rn(v.y); ll[1] = __float2half_rn(v.y - __half2float(hh[1]));
    hh[2] = __float2half_rn(v.z); ll[2] = __float2half_rn(v.z - __half2float(hh[2]));
    hh[3] = __float2half_rn(v.w); ll[3] = __float2half_rn(v.w - __half2float(hh[3]));
    *(uint2*)d          = *(uint2*)hh;
    *(uint2*)(d + Koff) = *(uint2*)ll;
}
__device__ __forceinline__ void split_store_B(float4 v, __half* d, int Koff) {
    __align__(8) __half hh[4];
    hh[0] = __float2half_rn(v.x); hh[1] = __float2half_rn(v.y);
    hh[2] = __float2half_rn(v.z); hh[3] = __float2half_rn(v.w);
    *(uint2*)d          = *(uint2*)hh;
    *(uint2*)(d + Koff) = *(uint2*)hh;
}

// ---------------- fused conversion kernel (round-8 form) ----------------
#define Q_R0 (BB * IN / 4)               // 393216
#define Q_R1 (Q_R0 + 512 * 768 / 4)      // 491520
#define Q_R2 (Q_R1 + 512 * 512 / 4)      // 557056
#define Q_TOT (Q_R2 + 512 * 256 / 4)     // 589824

__global__ __launch_bounds__(256) void conv_all(
    const float* __restrict__ E, const float* __restrict__ H, const float* __restrict__ Qm,
    const float* __restrict__ W1, const float* __restrict__ W2, const float* __restrict__ emb_r,
    __half* __restrict__ A1, __half* __restrict__ W1s,
    __half* __restrict__ W2s, __half* __restrict__ Ers)
{
    const int q = blockIdx.x * 256 + threadIdx.x;
    if (q < Q_R0) {
        const int m = q / 192, c = (q % 192) * 4;
        const float* src = (c < 256) ? (E + m * 256 + c)
                         : (c < 512) ? (H + m * 256 + (c - 256))
                                     : (Qm + m * 256 + (c - 512));
        float4 v = *(const float4*)src;
        split_store_A(v, A1 + (size_t)m * 1536 + c, 768);
    } else if (q < Q_R1) {
        const int q2 = q - Q_R0;
        const int n = q2 / 192, k = (q2 % 192) * 4;
        float4 v = *(const float4*)(W1 + (size_t)n * 768 + k);
        split_store_B(v, W1s + (size_t)n * 1536 + k, 768);
    } else if (q < Q_R2) {
        const int q2 = q - Q_R1;
        const int n = q2 / 128, k = (q2 % 128) * 4;
        float4 v = *(const float4*)(W2 + (size_t)n * 512 + k);
        split_store_B(v, W2s + (size_t)n * 1024 + k, 512);
    } else {
        const int q2 = q - Q_R2;
        const int n = q2 / 64, k = (q2 % 64) * 4;
        float4 v = make_float4(0.f, 0.f, 0.f, 0.f);
        if (n < 500) v = *(const float4*)(emb_r + (size_t)n * 256 + k);
        split_store_B(v, Ers + (size_t)n * 512 + k, 256);
    }
}

// ---------------- HMMA GEMM + co-scheduled emb_e conversion ----------------
// bids [0, 256): GEMM tile (m0 = (bid&31)*64, n0 = (bid>>5)*64) — unchanged math.
// bids [256, 576): grid-stride fp32->fp16 conversion of emb_e[ee_base, ee_base+ee_cnt).
// MODE 0: +b1, relu, split-store into g_A2 (W=512)
// MODE 1: +b2; cols<256 -> split into g_A3 (W=256); cols>=256 -> fp32 g_X2e
// MODE 2: fp32 -> g_P (stride 512)
template <int MODE>
__global__ __launch_bounds__(128) void gemm_mma(
    const __half* __restrict__ A, const __half* __restrict__ Bm,
    int ldk, int nchunks, const float* __restrict__ bias,
    __half* __restrict__ outs, float* __restrict__ outf,
    const float* __restrict__ eesrc, __half* __restrict__ eedst,
    size_t ee_base, size_t ee_cnt)
{
    const int bid = blockIdx.x;
    const int t = threadIdx.x;

    if (bid >= NGEMM) {
        // ---- converter path: no smem use, no syncs, pure streaming ----
        const int cb = bid - NGEMM;
        const size_t stride = (size_t)NCONV * 128 * 8;
        for (size_t i = ee_base + ((size_t)cb * 128 + t) * 8;
             i < ee_base + ee_cnt; i += stride) {
            float4 a = *(const float4*)(eesrc + i);
            float4 b = *(const float4*)(eesrc + i + 4);
            __align__(16) __half h[8];
            h[0] = __float2half_rn(a.x); h[1] = __float2half_rn(a.y);
            h[2] = __float2half_rn(a.z); h[3] = __float2half_rn(a.w);
            h[4] = __float2half_rn(b.x); h[5] = __float2half_rn(b.y);
            h[6] = __float2half_rn(b.z); h[7] = __float2half_rn(b.w);
            *(uint4*)(eedst + i) = *(uint4*)h;
        }
        return;
    }

    extern __shared__ __half sm[];
    const uint32_t smA = smem_u32(sm);
    const uint32_t smB = smA + NSTAGE * A_ST_B;

    const int warp = t >> 5, lane = t & 31;
    const int m0 = (bid & 31) * TM;
    const int n0 = (bid >> 5) * TN;
    const int wm = (warp >> 1) * 32;
    const int wn = (warp & 1) * 32;

    const int rA  = lane & 15;
    const int sA8 = (lane >> 4);
    const int rB  = (lane & 7) + ((lane >> 4) & 1) * 8;
    const int sB8 = ((lane >> 3) & 1);

    float acc[2][4][4] = {};

    auto load_stage = [&](int s, int chunk) {
        const size_t k0 = (size_t)chunk * TKC;
        const uint32_t dA = smA + s * A_ST_B;
        const uint32_t dB = smB + s * B_ST_B;
        #pragma unroll
        for (int i = 0; i < 4; i++) {
            int v = t + i * 128;
            int row = v >> 3, seg = v & 7;
            CP_ASYNC16(dA + swz(row, seg),
                       A + (size_t)(m0 + row) * ldk + k0 + seg * 8);
        }
        #pragma unroll
        for (int i = 0; i < 4; i++) {
            int v = t + i * 128;
            int row = v >> 3, seg = v & 7;
            CP_ASYNC16(dB + swz(row, seg),
                       Bm + (size_t)(n0 + row) * ldk + k0 + seg * 8);
        }
        CP_COMMIT();
    };

    load_stage(0, 0);
    load_stage(1, 1);

    for (int i = 0; i < nchunks; i++) {
        CP_WAIT(1);
        __syncthreads();
        if (i + 2 < nchunks) load_stage((i + 2) % NSTAGE, i + 2);
        else CP_COMMIT();

        const uint32_t sAst = smA + (i % NSTAGE) * A_ST_B;
        const uint32_t sBst = smB + (i % NSTAGE) * B_ST_B;
        #pragma unroll
        for (int ks = 0; ks < 4; ks++) {
            uint32_t a0[4], a1[4], b0[4], b1[4];
            const int segK = ks * 2;
            ldsm_x4(a0, sAst + swz(wm +      rA, segK + sA8));
            ldsm_x4(a1, sAst + swz(wm + 16 + rA, segK + sA8));
            ldsm_x4(b0, sBst + swz(wn +      rB, segK + sB8));
            ldsm_x4(b1, sBst + swz(wn + 16 + rB, segK + sB8));
            #pragma unroll
            for (int mi = 0; mi < 2; mi++) {
                const uint32_t* aa = mi ? a1 : a0;
                mma16816(acc[mi][0], aa, b0 + 0);
                mma16816(acc[mi][1], aa, b0 + 2);
                mma16816(acc[mi][2], aa, b1 + 0);
                mma16816(acc[mi][3], aa, b1 + 2);
            }
        }
    }

    #pragma unroll
    for (int mi = 0; mi < 2; mi++) {
        #pragma unroll
        for (int h = 0; h < 2; h++) {
            const int row = m0 + wm + 16 * mi + 8 * h + (lane >> 2);
            #pragma unroll
            for (int j = 0; j < 4; j++) {
                const int col = n0 + wn + 8 * j + 2 * (lane & 3);
                float v0 = acc[mi][j][2 * h];
                float v1 = acc[mi][j][2 * h + 1];
                if (MODE == 2) {
                    *(float2*)(outf + (size_t)row * 512 + col) = make_float2(v0, v1);
                } else {
                    v0 += __ldg(&bias[col]);
                    v1 += __ldg(&bias[col + 1]);
                    if (MODE == 0) { v0 = fmaxf(v0, 0.0f); v1 = fmaxf(v1, 0.0f); }
                    if (MODE == 1 && col >= 256) {
                        *(float2*)(outf + (size_t)row * 256 + (col - 256)) = make_float2(v0, v1);
                    } else {
                        const int W = (MODE == 0) ? 512 : 256;
                        __half h0 = __float2half_rn(v0);
                        __half h1 = __float2half_rn(v1);
                        __half l0 = __float2half_rn(v0 - __half2float(h0));
                        __half l1 = __float2half_rn(v1 - __half2float(h1));
                        __half2 hh; hh.x = h0; hh.y = h1;
                        __half2 ll; ll.x = l0; ll.y = l1;
                        __half* r0 = outs + (size_t)row * (2 * W) + col;
                        *(__half2*)(r0)     = hh;
                        *(__half2*)(r0 + W) = ll;
                    }
                }
            }
        }
    }
}

// ---------------- score + softmax + entropy (fp16 gather, mask-skipped) ----------------
__global__ __launch_bounds__(256) void score_softmax(
    const float* __restrict__ X2e, const float* __restrict__ P,
    const __half* __restrict__ emb16, const float* __restrict__ mask,
    const int* __restrict__ r_space, const int* __restrict__ e_space,
    float* __restrict__ out_dist, float* __restrict__ out_ent, int write_ent)
{
    const int b = blockIdx.x;
    __shared__ float x2e[256];
    __shared__ float sc[KK];
    __shared__ float red1[8], red2[8], red3[8];
    const int t = threadIdx.x;
    const int warp = t >> 5, lane = t & 31;

    x2e[t] = X2e[b * 256 + t];
    const int   kidx = warp * 32 + lane;
    const int   eall = e_space[b * KK + kidx];
    const float mval = mask[b * KK + kidx];
    const unsigned validb = __ballot_sync(0xFFFFFFFFu, mval != 0.0f);
    __syncthreads();

    // lane owns elements [lane*8, lane*8+8)
    const float4 xa = *(const float4*)&x2e[lane * 8];
    const float4 xb = *(const float4*)&x2e[lane * 8 + 4];

    for (int i = 0; i < 32; i++) {
        const int k = warp * 32 + i;
        if ((validb >> i) & 1u) {
            const int e = __shfl_sync(0xFFFFFFFFu, eall, i);
            const uint4 hv = *(const uint4*)(emb16 + (size_t)e * 256 + lane * 8);
            float2 p0 = __half22float2(*(const __half2*)&hv.x);
            float2 p1 = __half22float2(*(const __half2*)&hv.y);
            float2 p2 = __half22float2(*(const __half2*)&hv.z);
            float2 p3 = __half22float2(*(const __half2*)&hv.w);
            float s = p0.x * xa.x + p0.y * xa.y + p1.x * xa.z + p1.y * xa.w
                    + p2.x * xb.x + p2.y * xb.y + p3.x * xb.z + p3.y * xb.w;
            #pragma unroll
            for (int o = 16; o; o >>= 1) s += __shfl_xor_sync(0xFFFFFFFFu, s, o);
            if (lane == 0) sc[k] = s;
        } else {
            if (lane == 0) sc[k] = 0.0f;
        }
    }
    __syncthreads();

    const int r = r_space[b * KK + t];
    float s = sc[t] + P[b * 512 + r] - (1.0f - mask[b * KK + t]) * 1e31f;

    float mx = s;
#pragma unroll
    for (int o = 16; o; o >>= 1) mx = fmaxf(mx, __shfl_xor_sync(0xFFFFFFFFu, mx, o));
    if (lane == 0) red1[warp] = mx;
    __syncthreads();
    float bm = red1[0];
#pragma unroll
    for (int w = 1; w < 8; w++) bm = fmaxf(bm, red1[w]);

    const float p = expf(s - bm);
    float sum = p;
#pragma unroll
    for (int o = 16; o; o >>= 1) sum += __shfl_xor_sync(0xFFFFFFFFu, sum, o);
    if (lane == 0) red2[warp] = sum;
    __syncthreads();
    float bs = 0.f;
#pragma unroll
    for (int w = 0; w < 8; w++) bs += red2[w];

    const float dist = p / bs;
    out_dist[b * KK + t] = dist;

    float es = -dist * logf(dist + 1e-20f);
#pragma unroll
    for (int o = 16; o; o >>= 1) es += __shfl_xor_sync(0xFFFFFFFFu, es, o);
    if (lane == 0) red3[warp] = es;
    __syncthreads();
    if (t == 0 && write_ent) {
        float tot = 0.f;
#pragma unroll
        for (int w = 0; w < 8; w++) tot += red3[w];
        out_ent[b] = tot;
    }
}

// ---------------- launcher ----------------
extern "C" void kernel_launch(void* const* d_in, const int* in_sizes, int n_in,
                              void* d_out, int out_size)
{
    const float* E     = (const float*)d_in[0];
    const float* H     = (const float*)d_in[1];
    const float* Q     = (const float*)d_in[2];
    const float* W1    = (const float*)d_in[3];
    const float* b1    = (const float*)d_in[4];
    const float* W2    = (const float*)d_in[5];
    const float* b2    = (const float*)d_in[6];
    const float* emb_r = (const float*)d_in[7];
    const float* emb_e = (const float*)d_in[8];
    const float* mask  = (const float*)d_in[9];
    const int*   r_sp  = (const int*)d_in[10];
    const int*   e_sp  = (const int*)d_in[11];
    float* out = (float*)d_out;

    __half *gA1, *gW1s, *gA2, *gW2s, *gA3, *gErs, *gEe;
    float *gX2e, *gP;
    cudaGetSymbolAddress((void**)&gA1,  g_A1);
    cudaGetSymbolAddress((void**)&gW1s, g_W1s);
    cudaGetSymbolAddress((void**)&gA2,  g_A2);
    cudaGetSymbolAddress((void**)&gW2s, g_W2s);
    cudaGetSymbolAddress((void**)&gA3,  g_A3);
    cudaGetSymbolAddress((void**)&gErs, g_Ers);
    cudaGetSymbolAddress((void**)&gEe,  g_Ee);
    cudaGetSymbolAddress((void**)&gX2e, g_X2e);
    cudaGetSymbolAddress((void**)&gP,   g_P);

    cudaFuncSetAttribute(gemm_mma<0>, cudaFuncAttributeMaxDynamicSharedMemorySize, GEMM_SMEM);
    cudaFuncSetAttribute(gemm_mma<1>, cudaFuncAttributeMaxDynamicSharedMemorySize, GEMM_SMEM);
    cudaFuncSetAttribute(gemm_mma<2>, cudaFuncAttributeMaxDynamicSharedMemorySize, GEMM_SMEM);

    const int write_ent = (out_size >= BB * KK + BB) ? 1 : 0;

    // emb_e conversion slices (elements), proportional to GEMM durations
    const size_t e0 = 0;
    const size_t c0 = 10240000;           // G1 slice
    const size_t e1 = c0;
    const size_t c1 = 8192000;            // G2 slice
    const size_t e2 = e1 + c1;            // 18,432,000
    const size_t c2 = EE_TOT - e2;        // 7,168,000  (G3 slice)

    conv_all<<<Q_TOT / 256, 256>>>(E, H, Q, W1, W2, emb_r, gA1, gW1s, gW2s, gErs);

    gemm_mma<0><<<NGEMM + NCONV, 128, GEMM_SMEM>>>(gA1, gW1s, 1536, 24, b1, gA2, nullptr,
                                                   emb_e, gEe, e0, c0);
    gemm_mma<1><<<NGEMM + NCONV, 128, GEMM_SMEM>>>(gA2, gW2s, 1024, 16, b2, gA3, gX2e,
                                                   emb_e, gEe, e1, c1);
    gemm_mma<2><<<NGEMM + NCONV, 128, GEMM_SMEM>>>(gA3, gErs,  512,  8, nullptr, nullptr, gP,
                                                   emb_e, gEe, e2, c2);

    score_softmax<<<BB, 256>>>(gX2e, gP, gEe, mask, r_sp, e_sp,
                               out, out + (size_t)BB * KK, write_ent);
}

// round 17
// speedup vs baseline: 1.3535x; 1.3535x over previous
#include <cuda_runtime.h>
#include <cuda_fp16.h>
#include <math.h>
#include <stdint.h>

#define BB 2048
#define KK 256
#define AD 512
#define IN 768

#define TM 64
#define TN 64
#define TKC 64
#define NSTAGE 3
#define A_ST_B (TM * 128)
#define B_ST_B (TN * 128)
#define GEMM_SMEM (NSTAGE * (A_ST_B + B_ST_B))   // 49152 B

// ---------------- scratch (device globals: no allocs allowed) ----------------
__device__ __half g_A1 [(size_t)BB * 1536];   // split concat(E,H,Q) [hi|lo]
__device__ __half g_W1s[(size_t)AD * 1536];   // split W1            [hi|hi]
__device__ __half g_A2 [(size_t)BB * 1024];
__device__ __half g_W2s[(size_t)AD * 1024];
__device__ __half g_A3 [(size_t)BB * 512];
__device__ __half g_Ers[(size_t)512 * 512];
__device__ float g_X2e[(size_t)BB * 256];
__device__ float g_P  [(size_t)BB * 512];

// ---------------- helpers ----------------
__device__ __forceinline__ uint32_t smem_u32(const void* p) {
    uint32_t a;
    asm("{ .reg .u64 t; cvta.to.shared.u64 t, %1; cvt.u32.u64 %0, t; }" : "=r"(a) : "l"(p));
    return a;
}
#define CP_ASYNC16(dst, src) \
    asm volatile("cp.async.cg.shared.global [%0], [%1], 16;" :: "r"(dst), "l"(src) : "memory")
#define CP_COMMIT()  asm volatile("cp.async.commit_group;" ::: "memory")
#define CP_WAIT(n)   asm volatile("cp.async.wait_group %0;" :: "n"(n) : "memory")

__device__ __forceinline__ void ldsm_x4(uint32_t* r, uint32_t addr) {
    asm volatile("ldmatrix.sync.aligned.m8n8.x4.shared.b16 {%0,%1,%2,%3}, [%4];"
                 : "=r"(r[0]), "=r"(r[1]), "=r"(r[2]), "=r"(r[3]) : "r"(addr));
}
__device__ __forceinline__ void mma16816(float* c, const uint32_t* a, const uint32_t* b) {
    asm volatile(
        "mma.sync.aligned.m16n8k16.row.col.f32.f16.f16.f32 "
        "{%0,%1,%2,%3}, {%4,%5,%6,%7}, {%8,%9}, {%0,%1,%2,%3};"
        : "+f"(c[0]), "+f"(c[1]), "+f"(c[2]), "+f"(c[3])
        : "r"(a[0]), "r"(a[1]), "r"(a[2]), "r"(a[3]), "r"(b[0]), "r"(b[1]));
}
__device__ __forceinline__ uint32_t swz(int row, int seg) {
    return (uint32_t)(row * 128 + ((seg ^ (row & 7)) << 4));
}
__device__ __forceinline__ void split_store_A(float4 v, __half* d, int Koff) {
    __align__(8) __half hh[4], ll[4];
    hh[0] = __float2half_rn(v.x); ll[0] = __float2half_rn(v.x - __half2float(hh[0]));
    hh[1] = __float2half_rn(v.y); ll[1] = __float2half_rn(v.y - __half2float(hh[1]));
    hh[2] = __float2half_rn(v.z); ll[2] = __float2half_rn(v.z - __half2float(hh[2]));
    hh[3] = __float2half_rn(v.w); ll[3] = __float2half_rn(v.w - __half2float(hh[3]));
    *(uint2*)d          = *(uint2*)hh;
    *(uint2*)(d + Koff) = *(uint2*)ll;
}
__device__ __forceinline__ void split_store_B(float4 v, __half* d, int Koff) {
    __align__(8) __half hh[4];
    hh[0] = __float2half_rn(v.x); hh[1] = __float2half_rn(v.y);
    hh[2] = __float2half_rn(v.z); hh[3] = __float2half_rn(v.w);
    *(uint2*)d          = *(uint2*)hh;
    *(uint2*)(d + Koff) = *(uint2*)hh;
}

// ---------------- fused conversion kernel ----------------
#define Q_R0 (BB * IN / 4)               // 393216
#define Q_R1 (Q_R0 + 512 * 768 / 4)      // 491520
#define Q_R2 (Q_R1 + 512 * 512 / 4)      // 557056
#define Q_TOT (Q_R2 + 512 * 256 / 4)     // 589824

__global__ __launch_bounds__(256) void conv_all(
    const float* __restrict__ E, const float* __restrict__ H, const float* __restrict__ Qm,
    const float* __restrict__ W1, const float* __restrict__ W2, const float* __restrict__ emb_r,
    __half* __restrict__ A1, __half* __restrict__ W1s,
    __half* __restrict__ W2s, __half* __restrict__ Ers)
{
    const int q = blockIdx.x * 256 + threadIdx.x;
    if (q < Q_R0) {
        const int m = q / 192, c = (q % 192) * 4;
        const float* src = (c < 256) ? (E + m * 256 + c)
                         : (c < 512) ? (H + m * 256 + (c - 256))
                                     : (Qm + m * 256 + (c - 512));
        float4 v = *(const float4*)src;
        split_store_A(v, A1 + (size_t)m * 1536 + c, 768);
    } else if (q < Q_R1) {
        const int q2 = q - Q_R0;
        const int n = q2 / 192, k = (q2 % 192) * 4;
        float4 v = *(const float4*)(W1 + (size_t)n * 768 + k);
        split_store_B(v, W1s + (size_t)n * 1536 + k, 768);
    } else if (q < Q_R2) {
        const int q2 = q - Q_R1;
        const int n = q2 / 128, k = (q2 % 128) * 4;
        float4 v = *(const float4*)(W2 + (size_t)n * 512 + k);
        split_store_B(v, W2s + (size_t)n * 1024 + k, 512);
    } else {
        const int q2 = q - Q_R2;
        const int n = q2 / 64, k = (q2 % 64) * 4;
        float4 v = make_float4(0.f, 0.f, 0.f, 0.f);
        if (n < 500) v = *(const float4*)(emb_r + (size_t)n * 256 + k);
        split_store_B(v, Ers + (size_t)n * 512 + k, 256);
    }
}

// ---------------- HMMA GEMM with PDL prologue ----------------
// PREB=1: B operand is from conv (final before this kernel's predecessor) ->
//         prefetch B stages 0/1 BEFORE grid-dependency sync, A stages after.
// MODE 0: +b1, relu, split-store into g_A2 (W=512)
// MODE 1: +b2; cols<256 -> split into g_A3 (W=256); cols>=256 -> fp32 g_X2e
// MODE 2: fp32 -> g_P (stride 512)
template <int MODE, int PREB>
__global__ __launch_bounds__(128) void gemm_mma(
    const __half* __restrict__ A, const __half* __restrict__ Bm,
    int ldk, int nchunks, const float* __restrict__ bias,
    __half* __restrict__ outs, float* __restrict__ outf)
{
#if __CUDA_ARCH__ >= 900
    cudaTriggerProgrammaticLaunchCompletion();
#endif
    extern __shared__ __half sm[];
    const uint32_t smA = smem_u32(sm);
    const uint32_t smB = smA + NSTAGE * A_ST_B;

    const int t = threadIdx.x;
    const int warp = t >> 5, lane = t & 31;
    const int m0 = blockIdx.x * TM;
    const int n0 = blockIdx.y * TN;
    const int wm = (warp >> 1) * 32;
    const int wn = (warp & 1) * 32;

    const int rA  = lane & 15;
    const int sA8 = (lane >> 4);
    const int rB  = (lane & 7) + ((lane >> 4) & 1) * 8;
    const int sB8 = ((lane >> 3) & 1);

    float acc[2][4][4] = {};

    auto load_A = [&](int s, int chunk) {
        const size_t k0 = (size_t)chunk * TKC;
        const uint32_t dA = smA + s * A_ST_B;
        #pragma unroll
        for (int i = 0; i < 4; i++) {
            int v = t + i * 128;
            int row = v >> 3, seg = v & 7;
            CP_ASYNC16(dA + swz(row, seg),
                       A + (size_t)(m0 + row) * ldk + k0 + seg * 8);
        }
        CP_COMMIT();
    };
    auto load_B = [&](int s, int chunk) {
        const size_t k0 = (size_t)chunk * TKC;
        const uint32_t dB = smB + s * B_ST_B;
        #pragma unroll
        for (int i = 0; i < 4; i++) {
            int v = t + i * 128;
            int row = v >> 3, seg = v & 7;
            CP_ASYNC16(dB + swz(row, seg),
                       Bm + (size_t)(n0 + row) * ldk + k0 + seg * 8);
        }
        CP_COMMIT();
    };
    auto load_stage = [&](int s, int chunk) {
        const size_t k0 = (size_t)chunk * TKC;
        const uint32_t dA = smA + s * A_ST_B;
        const uint32_t dB = smB + s * B_ST_B;
        #pragma unroll
        for (int i = 0; i < 4; i++) {
            int v = t + i * 128;
            int row = v >> 3, seg = v & 7;
            CP_ASYNC16(dA + swz(row, seg),
                       A + (size_t)(m0 + row) * ldk + k0 + seg * 8);
        }
        #pragma unroll
        for (int i = 0; i < 4; i++) {
            int v = t + i * 128;
            int row = v >> 3, seg = v & 7;
            CP_ASYNC16(dB + swz(row, seg),
                       Bm + (size_t)(n0 + row) * ldk + k0 + seg * 8);
        }
        CP_COMMIT();
    };

    if (PREB) {
        // B is independent of the predecessor kernel: prefetch before the sync.
        load_B(0, 0);
        load_B(1, 1);
#if __CUDA_ARCH__ >= 900
        cudaGridDependencySynchronize();
#endif
        load_A(0, 0);
        load_A(1, 1);
        // pending groups: {B0, B1, A0, A1} -> CP_WAIT(1) at i=0 retires B0,B1,A0
    } else {
#if __CUDA_ARCH__ >= 900
        cudaGridDependencySynchronize();
#endif
        load_stage(0, 0);
        load_stage(1, 1);
    }

    for (int i = 0; i < nchunks; i++) {
        CP_WAIT(1);
        __syncthreads();
        if (i + 2 < nchunks) load_stage((i + 2) % NSTAGE, i + 2);
        else CP_COMMIT();

        const uint32_t sAst = smA + (i % NSTAGE) * A_ST_B;
        const uint32_t sBst = smB + (i % NSTAGE) * B_ST_B;
        #pragma unroll
        for (int ks = 0; ks < 4; ks++) {
            uint32_t a0[4], a1[4], b0[4], b1[4];
            const int segK = ks * 2;
            ldsm_x4(a0, sAst + swz(wm +      rA, segK + sA8));
            ldsm_x4(a1, sAst + swz(wm + 16 + rA, segK + sA8));
            ldsm_x4(b0, sBst + swz(wn +      rB, segK + sB8));
            ldsm_x4(b1, sBst + swz(wn + 16 + rB, segK + sB8));
            #pragma unroll
            for (int mi = 0; mi < 2; mi++) {
                const uint32_t* aa = mi ? a1 : a0;
                mma16816(acc[mi][0], aa, b0 + 0);
                mma16816(acc[mi][1], aa, b0 + 2);
                mma16816(acc[mi][2], aa, b1 + 0);
                mma16816(acc[mi][3], aa, b1 + 2);
            }
        }
    }

    // ---------------- epilogue ----------------
    #pragma unroll
    for (int mi = 0; mi < 2; mi++) {
        #pragma unroll
        for (int h = 0; h < 2; h++) {
            const int row = m0 + wm + 16 * mi + 8 * h + (lane >> 2);
            #pragma unroll
            for (int j = 0; j < 4; j++) {
                const int col = n0 + wn + 8 * j + 2 * (lane & 3);
                float v0 = acc[mi][j][2 * h];
                float v1 = acc[mi][j][2 * h + 1];
                if (MODE == 2) {
                    *(float2*)(outf + (size_t)row * 512 + col) = make_float2(v0, v1);
                } else {
                    v0 += __ldg(&bias[col]);
                    v1 += __ldg(&bias[col + 1]);
                    if (MODE == 0) { v0 = fmaxf(v0, 0.0f); v1 = fmaxf(v1, 0.0f); }
                    if (MODE == 1 && col >= 256) {
                        *(float2*)(outf + (size_t)row * 256 + (col - 256)) = make_float2(v0, v1);
                    } else {
                        const int W = (MODE == 0) ? 512 : 256;
                        __half h0 = __float2half_rn(v0);
                        __half h1 = __float2half_rn(v1);
                        __half l0 = __float2half_rn(v0 - __half2float(h0));
                        __half l1 = __float2half_rn(v1 - __half2float(h1));
                        __half2 hh; hh.x = h0; hh.y = h1;
                        __half2 ll; ll.x = l0; ll.y = l1;
                        __half* r0 = outs + (size_t)row * (2 * W) + col;
                        *(__half2*)(r0)     = hh;
                        *(__half2*)(r0 + W) = ll;
                    }
                }
            }
        }
    }
}

// ---------------- score + softmax + entropy (PDL prologue on inputs) ----------------
__global__ __launch_bounds__(256) void score_softmax(
    const float* __restrict__ X2e, const float* __restrict__ P,
    const float* __restrict__ emb_e, const float* __restrict__ mask,
    const int* __restrict__ r_space, const int* __restrict__ e_space,
    float* __restrict__ out_dist, float* __restrict__ out_ent, int write_ent)
{
    const int b = blockIdx.x;
    __shared__ float x2e[256];
    __shared__ float sc[KK];
    __shared__ float red1[8], red2[8], red3[8];
    const int t = threadIdx.x;
    const int warp = t >> 5, lane = t & 31;

    // prologue: pure-input loads overlap the predecessor GEMM (kidx == t)
    const int   eall = e_space[b * KK + t];
    const float mval = mask[b * KK + t];
    const int   r    = r_space[b * KK + t];
    const unsigned validb = __ballot_sync(0xFFFFFFFFu, mval != 0.0f);

#if __CUDA_ARCH__ >= 900
    cudaGridDependencySynchronize();
#endif

    x2e[t] = X2e[b * 256 + t];
    __syncthreads();

    const float4 xa = *(const float4*)&x2e[lane * 4];
    const float4 xb = *(const float4*)&x2e[lane * 4 + 128];

    for (int i = 0; i < 32; i++) {
        const int k = warp * 32 + i;
        if ((validb >> i) & 1u) {
            const int e = __shfl_sync(0xFFFFFFFFu, eall, i);
            const float4* er = (const float4*)(emb_e + (size_t)e * 256);
            const float4 v0 = er[lane];
            const float4 v1 = er[lane + 32];
            float s = v0.x * xa.x + v0.y * xa.y + v0.z * xa.z + v0.w * xa.w
                    + v1.x * xb.x + v1.y * xb.y + v1.z * xb.z + v1.w * xb.w;
            #pragma unroll
            for (int o = 16; o; o >>= 1) s += __shfl_xor_sync(0xFFFFFFFFu, s, o);
            if (lane == 0) sc[k] = s;
        } else {
            if (lane == 0) sc[k] = 0.0f;
        }
    }
    __syncthreads();

    float s = sc[t] + P[b * 512 + r] - (1.0f - mval) * 1e31f;

    float mx = s;
#pragma unroll
    for (int o = 16; o; o >>= 1) mx = fmaxf(mx, __shfl_xor_sync(0xFFFFFFFFu, mx, o));
    if (lane == 0) red1[warp] = mx;
    __syncthreads();
    float bm = red1[0];
#pragma unroll
    for (int w = 1; w < 8; w++) bm = fmaxf(bm, red1[w]);

    const float p = expf(s - bm);
    float sum = p;
#pragma unroll
    for (int o = 16; o; o >>= 1) sum += __shfl_xor_sync(0xFFFFFFFFu, sum, o);
    if (lane == 0) red2[warp] = sum;
    __syncthreads();
    float bs = 0.f;
#pragma unroll
    for (int w = 0; w < 8; w++) bs += red2[w];

    const float dist = p / bs;
    out_dist[b * KK + t] = dist;

    float es = -dist * logf(dist + 1e-20f);
#pragma unroll
    for (int o = 16; o; o >>= 1) es += __shfl_xor_sync(0xFFFFFFFFu, es, o);
    if (lane == 0) red3[warp] = es;
    __syncthreads();
    if (t == 0 && write_ent) {
        float tot = 0.f;
#pragma unroll
        for (int w = 0; w < 8; w++) tot += red3[w];
        out_ent[b] = tot;
    }
}

// ---------------- launcher (PDL chain) ----------------
extern "C" void kernel_launch(void* const* d_in, const int* in_sizes, int n_in,
                              void* d_out, int out_size)
{
    const float* E     = (const float*)d_in[0];
    const float* H     = (const float*)d_in[1];
    const float* Q     = (const float*)d_in[2];
    const float* W1    = (const float*)d_in[3];
    const float* b1    = (const float*)d_in[4];
    const float* W2    = (const float*)d_in[5];
    const float* b2    = (const float*)d_in[6];
    const float* emb_r = (const float*)d_in[7];
    const float* emb_e = (const float*)d_in[8];
    const float* mask  = (const float*)d_in[9];
    const int*   r_sp  = (const int*)d_in[10];
    const int*   e_sp  = (const int*)d_in[11];
    float* out = (float*)d_out;

    __half *gA1, *gW1s, *gA2, *gW2s, *gA3, *gErs;
    float *gX2e, *gP;
    cudaGetSymbolAddress((void**)&gA1,  g_A1);
    cudaGetSymbolAddress((void**)&gW1s, g_W1s);
    cudaGetSymbolAddress((void**)&gA2,  g_A2);
    cudaGetSymbolAddress((void**)&gW2s, g_W2s);
    cudaGetSymbolAddress((void**)&gA3,  g_A3);
    cudaGetSymbolAddress((void**)&gErs, g_Ers);
    cudaGetSymbolAddress((void**)&gX2e, g_X2e);
    cudaGetSymbolAddress((void**)&gP,   g_P);

    cudaFuncSetAttribute((const void*)gemm_mma<0,0>, cudaFuncAttributeMaxDynamicSharedMemorySize, GEMM_SMEM);
    cudaFuncSetAttribute((const void*)gemm_mma<1,1>, cudaFuncAttributeMaxDynamicSharedMemorySize, GEMM_SMEM);
    cudaFuncSetAttribute((const void*)gemm_mma<2,1>, cudaFuncAttributeMaxDynamicSharedMemorySize, GEMM_SMEM);

    const int write_ent = (out_size >= BB * KK + BB) ? 1 : 0;

    conv_all<<<Q_TOT / 256, 256>>>(E, H, Q, W1, W2, emb_r, gA1, gW1s, gW2s, gErs);

    cudaLaunchAttribute pdl[1];
    pdl[0].id = cudaLaunchAttributeProgrammaticStreamSerialization;
    pdl[0].val.programmaticStreamSerializationAllowed = 1;

    {   // G1 (PDL-dependent on conv; no safe prologue -> sync first)
        cudaLaunchConfig_t cfg = {};
        cfg.gridDim = dim3(BB / TM, AD / TN);
        cfg.blockDim = dim3(128);
        cfg.dynamicSmemBytes = GEMM_SMEM;
        cfg.stream = 0;
        cfg.attrs = pdl; cfg.numAttrs = 1;
        cudaLaunchKernelEx(&cfg, gemm_mma<0,0>,
                           (const __half*)gA1, (const __half*)gW1s, (int)1536, (int)24,
                           (const float*)b1, (__half*)gA2, (float*)nullptr);
    }
    {   // G2 (prefetch W2s before sync)
        cudaLaunchConfig_t cfg = {};
        cfg.gridDim = dim3(BB / TM, AD / TN);
        cfg.blockDim = dim3(128);
        cfg.dynamicSmemBytes = GEMM_SMEM;
        cfg.stream = 0;
        cfg.attrs = pdl; cfg.numAttrs = 1;
        cudaLaunchKernelEx(&cfg, gemm_mma<1,1>,
                           (const __half*)gA2, (const __half*)gW2s, (int)1024, (int)16,
                           (const float*)b2, (__half*)gA3, (float*)gX2e);
    }
    {   // G3 (prefetch Ers before sync)
        cudaLaunchConfig_t cfg = {};
        cfg.gridDim = dim3(BB / TM, AD / TN);
        cfg.blockDim = dim3(128);
        cfg.dynamicSmemBytes = GEMM_SMEM;
        cfg.stream = 0;
        cfg.attrs = pdl; cfg.numAttrs = 1;
        cudaLaunchKernelEx(&cfg, gemm_mma<2,1>,
                           (const __half*)gA3, (const __half*)gErs, (int)512, (int)8,
                           (const float*)nullptr, (__half*)nullptr, (float*)gP);
    }
    {   // score (prologue loads inputs before sync)
        cudaLaunchConfig_t cfg = {};
        cfg.gridDim = dim3(BB);
        cfg.blockDim = dim3(256);
        cfg.dynamicSmemBytes = 0;
        cfg.stream = 0;
        cfg.attrs = pdl; cfg.numAttrs = 1;
        cudaLaunchKernelEx(&cfg, score_softmax,
                           (const float*)gX2e, (const float*)gP, emb_e, mask,
                           r_sp, e_sp, out, out + (size_t)BB * KK, write_ent);
    }
}